// round 14
// baseline (speedup 1.0000x reference)
#include <cuda_runtime.h>
#include <math.h>

#define V_MAX   100000
#define E_MAX   1600000
#define IN_CH   128
#define HEADS   4
#define HC      64
#define NEG_SLOPE 0.2f
#define SCAN_BLK 256
#define GROWS   128
#define WPAD    72

// ---------------- scratch (device globals; no allocation) ----------------
__device__ float g_z[(size_t)V_MAX * HC];
__device__ float g_esrc[V_MAX * HEADS];
__device__ float g_edst[V_MAX * HEADS];
__device__ int   g_deg[V_MAX];
__device__ int   g_excl[V_MAX];
__device__ int   g_bsums[512];
__device__ int   g_rowstart[V_MAX];
__device__ int   g_cursor[V_MAX];
__device__ int   g_csr_src[E_MAX];

// ---------------- CSR build ----------------
__global__ void zero_deg_kernel(int v) {
    int i = blockIdx.x * blockDim.x + threadIdx.x;
    if (i < v) g_deg[i] = 0;
}

__global__ void count_kernel(const int* __restrict__ ei, int ecnt) {
    int e = blockIdx.x * blockDim.x + threadIdx.x;
    if (e < ecnt) atomicAdd(&g_deg[ei[ecnt + e]], 1);
}

__global__ void scan1_kernel(int v) {
    __shared__ int sh[SCAN_BLK];
    int t = threadIdx.x;
    int i = blockIdx.x * SCAN_BLK + t;
    int val = (i < v) ? g_deg[i] : 0;
    sh[t] = val;
    __syncthreads();
#pragma unroll
    for (int off = 1; off < SCAN_BLK; off <<= 1) {
        int y = (t >= off) ? sh[t - off] : 0;
        __syncthreads();
        sh[t] += y;
        __syncthreads();
    }
    if (i < v) g_excl[i] = sh[t] - val;
    if (t == SCAN_BLK - 1) g_bsums[blockIdx.x] = sh[t];
}

__global__ void scan3_kernel(int v) {
    __shared__ int red[SCAN_BLK];
    const int b = blockIdx.x;
    const int t = threadIdx.x;
    int sum = 0;
    for (int i = t; i < b; i += SCAN_BLK) sum += g_bsums[i];
    red[t] = sum;
    __syncthreads();
#pragma unroll
    for (int off = SCAN_BLK / 2; off; off >>= 1) {
        if (t < off) red[t] += red[t + off];
        __syncthreads();
    }
    int prefix = red[0];
    int i = b * SCAN_BLK + t;
    if (i < v) {
        int r = g_excl[i] + prefix;
        g_rowstart[i] = r;
        g_cursor[i]   = r;
    }
}

__global__ void scatter_kernel(const int* __restrict__ ei, int ecnt) {
    int e = blockIdx.x * blockDim.x + threadIdx.x;
    if (e >= ecnt) return;
    int s = ei[e];
    int d = ei[ecnt + e];
    int pos = atomicAdd(&g_cursor[d], 1);
    g_csr_src[pos] = s;
}

// ---------------- helpers for tf32 mma ----------------
__device__ __forceinline__ unsigned cvt_tf32(float f) {
    unsigned u;
    asm("cvt.rna.tf32.f32 %0, %1;" : "=r"(u) : "f"(f));
    return u;
}

__device__ __forceinline__ void mma_tf32(float& c0, float& c1, float& c2, float& c3,
                                         unsigned a0, unsigned a1, unsigned a2, unsigned a3,
                                         unsigned b0, unsigned b1) {
    asm("mma.sync.aligned.m16n8k8.row.col.f32.tf32.tf32.f32 "
        "{%0,%1,%2,%3}, {%4,%5,%6,%7}, {%8,%9}, {%0,%1,%2,%3};"
        : "+f"(c0), "+f"(c1), "+f"(c2), "+f"(c3)
        : "r"(a0), "r"(a1), "r"(a2), "r"(a3), "r"(b0), "r"(b1));
}

// ---------------- fused GEMM + logits (tf32, 3xTF32) — R11 proven, frozen
__global__ void __launch_bounds__(256, 2)
gemm_logits_kernel(const float* __restrict__ x,
                   const float* __restrict__ W,
                   const float* __restrict__ a_src,
                   const float* __restrict__ a_dst,
                   int v)
{
    extern __shared__ float sm[];
    float* Whi = sm;
    float* Wlo = Whi + IN_CH * WPAD;
    float* as  = Wlo + IN_CH * WPAD;
    float* ad  = as + 64;

    const int tid  = threadIdx.x;
    const int wid  = tid >> 5;
    const int lane = tid & 31;
    const int g = lane >> 2;
    const int t = lane & 3;
    const int row0 = blockIdx.x * GROWS;

    for (int i = tid; i < IN_CH * HC; i += 256) {
        int k = i >> 6, n = i & 63;
        float w = W[i];
        unsigned hu = cvt_tf32(w);
        float hf = __uint_as_float(hu);
        Whi[k * WPAD + n] = hf;
        Wlo[k * WPAD + n] = __uint_as_float(cvt_tf32(w - hf));
    }
    if (tid < 64)       as[tid]      = a_src[tid];
    else if (tid < 128) ad[tid - 64] = a_dst[tid - 64];
    __syncthreads();

    float c0[8], c1[8], c2[8], c3[8];
#pragma unroll
    for (int nt = 0; nt < 8; ++nt) { c0[nt] = c1[nt] = c2[nt] = c3[nt] = 0.f; }

    const int r_lo = row0 + wid * 16 + g;
    const int r_hi = r_lo + 8;
    const bool vlo = r_lo < v, vhi = r_hi < v;
    const float* xlo = x + (size_t)r_lo * IN_CH;
    const float* xhi = x + (size_t)r_hi * IN_CH;

#pragma unroll 2
    for (int ks = 0; ks < IN_CH / 8; ++ks) {
        const int k0 = ks * 8;
        float a0f = vlo ? xlo[k0 + t]     : 0.f;
        float a1f = vhi ? xhi[k0 + t]     : 0.f;
        float a2f = vlo ? xlo[k0 + t + 4] : 0.f;
        float a3f = vhi ? xhi[k0 + t + 4] : 0.f;

        unsigned a0h = cvt_tf32(a0f), a1h = cvt_tf32(a1f);
        unsigned a2h = cvt_tf32(a2f), a3h = cvt_tf32(a3f);
        unsigned a0l = cvt_tf32(a0f - __uint_as_float(a0h));
        unsigned a1l = cvt_tf32(a1f - __uint_as_float(a1h));
        unsigned a2l = cvt_tf32(a2f - __uint_as_float(a2h));
        unsigned a3l = cvt_tf32(a3f - __uint_as_float(a3h));

        const int krow0 = (k0 + t) * WPAD;
        const int krow1 = (k0 + t + 4) * WPAD;
#pragma unroll
        for (int nt = 0; nt < 8; ++nt) {
            int col = nt * 8 + g;
            unsigned b0h = __float_as_uint(Whi[krow0 + col]);
            unsigned b1h = __float_as_uint(Whi[krow1 + col]);
            unsigned b0l = __float_as_uint(Wlo[krow0 + col]);
            unsigned b1l = __float_as_uint(Wlo[krow1 + col]);
            mma_tf32(c0[nt], c1[nt], c2[nt], c3[nt], a0h, a1h, a2h, a3h, b0h, b1h);
            mma_tf32(c0[nt], c1[nt], c2[nt], c3[nt], a0h, a1h, a2h, a3h, b0l, b1l);
            mma_tf32(c0[nt], c1[nt], c2[nt], c3[nt], a0l, a1l, a2l, a3l, b0h, b1h);
        }
    }

    if (vlo) {
#pragma unroll
        for (int nt = 0; nt < 8; ++nt)
            *(float2*)&g_z[(size_t)r_lo * HC + nt * 8 + 2 * t] = make_float2(c0[nt], c1[nt]);
    }
    if (vhi) {
#pragma unroll
        for (int nt = 0; nt < 8; ++nt)
            *(float2*)&g_z[(size_t)r_hi * HC + nt * 8 + 2 * t] = make_float2(c2[nt], c3[nt]);
    }

#pragma unroll
    for (int h = 0; h < HEADS; ++h) {
        float s0 = as[h * 16 + 2 * t],     s1 = as[h * 16 + 2 * t + 1];
        float s2 = as[h * 16 + 8 + 2 * t], s3 = as[h * 16 + 8 + 2 * t + 1];
        float d0 = ad[h * 16 + 2 * t],     d1 = ad[h * 16 + 2 * t + 1];
        float d2 = ad[h * 16 + 8 + 2 * t], d3 = ad[h * 16 + 8 + 2 * t + 1];

        float psl = c0[2*h]*s0 + c1[2*h]*s1 + c0[2*h+1]*s2 + c1[2*h+1]*s3;
        float pdl = c0[2*h]*d0 + c1[2*h]*d1 + c0[2*h+1]*d2 + c1[2*h+1]*d3;
        float psh = c2[2*h]*s0 + c3[2*h]*s1 + c2[2*h+1]*s2 + c3[2*h+1]*s3;
        float pdh = c2[2*h]*d0 + c3[2*h]*d1 + c2[2*h+1]*d2 + c3[2*h+1]*d3;

        psl += __shfl_xor_sync(0xffffffffu, psl, 1);
        psl += __shfl_xor_sync(0xffffffffu, psl, 2);
        pdl += __shfl_xor_sync(0xffffffffu, pdl, 1);
        pdl += __shfl_xor_sync(0xffffffffu, pdl, 2);
        psh += __shfl_xor_sync(0xffffffffu, psh, 1);
        psh += __shfl_xor_sync(0xffffffffu, psh, 2);
        pdh += __shfl_xor_sync(0xffffffffu, pdh, 1);
        pdh += __shfl_xor_sync(0xffffffffu, pdh, 2);

        if (t == 0) {
            if (vlo) {
                g_esrc[r_lo * HEADS + h] = psl;
                g_edst[r_lo * HEADS + h] = pdl;
            }
            if (vhi) {
                g_esrc[r_hi * HEADS + h] = psh;
                g_edst[r_hi * HEADS + h] = pdh;
            }
        }
    }
}

// ---------------- fused softmax + aggregation (overlapped latency chains)
// Per 32-edge batch: stage src indices, issue own-lane esrc gather, then
// IMMEDIATELY issue all z-row gathers (they depend only on src indices);
// compute exp/denominator while z loads are in flight; FMA-consume last.
// Padding lanes use s=0 with ex=0 (zero contribution; z[0] row is L1-hot).
__global__ void node_agg_kernel(float* __restrict__ out, int v) {
    __shared__ int   sh_s[8][32];
    __shared__ float sh_a[8][32][4];

    const int wid  = threadIdx.x >> 5;
    const int lane = threadIdx.x & 31;
    const int n = blockIdx.x * 8 + wid;
    if (n >= v) return;

    const int start = g_rowstart[n];
    const int degn  = g_deg[n];
    const float4 ed = *(const float4*)&g_edst[n * 4];
    const int head  = lane >> 3;
    const float* zb = g_z + (size_t)lane * 2;

    float acc0 = 0.f, acc1 = 0.f;
    float d0 = 0.f, d1 = 0.f, d2 = 0.f, d3 = 0.f;

    for (int i0 = 0; i0 < degn; i0 += 32) {
        const int cnt = min(degn - i0, 32);
        const int idx = i0 + lane;
        const bool valid = idx < degn;

        int s = 0;
        if (valid) s = __ldg(&g_csr_src[start + idx]);
        sh_s[wid][lane] = s;
        float4 es = *(const float4*)&g_esrc[s * 4];   // random gather, in flight
        __syncwarp();

        // ---- group 1 z gathers (issued while es is in flight) ----
        int sj0[16];
#pragma unroll
        for (int u = 0; u < 16; ++u) sj0[u] = sh_s[wid][u];
        float2 zj0[16];
#pragma unroll
        for (int u = 0; u < 16; ++u) zj0[u] = *(const float2*)(zb + (size_t)sj0[u] * HC);

        // ---- exp weights (consume es) ----
        float ex0 = 0.f, ex1 = 0.f, ex2 = 0.f, ex3 = 0.f;
        if (valid) {
            float w;
            w = es.x + ed.x; w = w > 0.f ? w : NEG_SLOPE * w; ex0 = __expf(w);
            w = es.y + ed.y; w = w > 0.f ? w : NEG_SLOPE * w; ex1 = __expf(w);
            w = es.z + ed.z; w = w > 0.f ? w : NEG_SLOPE * w; ex2 = __expf(w);
            w = es.w + ed.w; w = w > 0.f ? w : NEG_SLOPE * w; ex3 = __expf(w);
        }
        d0 += ex0; d1 += ex1; d2 += ex2; d3 += ex3;
        *(float4*)&sh_a[wid][lane][0] = make_float4(ex0, ex1, ex2, ex3);

        // ---- group 2 z gathers (only if batch has >16 edges) ----
        float2 zj1[16];
        const bool have2 = cnt > 16;
        if (have2) {
            int sj1[16];
#pragma unroll
            for (int u = 0; u < 16; ++u) sj1[u] = sh_s[wid][16 + u];
#pragma unroll
            for (int u = 0; u < 16; ++u) zj1[u] = *(const float2*)(zb + (size_t)sj1[u] * HC);
        }

        __syncwarp();   // publish sh_a

        // ---- FMA consume ----
#pragma unroll
        for (int u = 0; u < 16; ++u) {
            float a = sh_a[wid][u][head];
            acc0 += zj0[u].x * a;
            acc1 += zj0[u].y * a;
        }
        if (have2) {
#pragma unroll
            for (int u = 0; u < 16; ++u) {
                float a = sh_a[wid][16 + u][head];
                acc0 += zj1[u].x * a;
                acc1 += zj1[u].y * a;
            }
        }
        __syncwarp();   // protect sh_s/sh_a before next batch overwrites
    }

#pragma unroll
    for (int o = 16; o; o >>= 1) {
        d0 += __shfl_xor_sync(0xffffffffu, d0, o);
        d1 += __shfl_xor_sync(0xffffffffu, d1, o);
        d2 += __shfl_xor_sync(0xffffffffu, d2, o);
        d3 += __shfl_xor_sync(0xffffffffu, d3, o);
    }
    float den = head == 0 ? d0 : head == 1 ? d1 : head == 2 ? d2 : d3;
    float r = __frcp_rn(den + 1e-9f);
    acc0 *= r; acc1 *= r;
    acc0 = acc0 > 0.f ? acc0 : expm1f(acc0);
    acc1 = acc1 > 0.f ? acc1 : expm1f(acc1);
    *(float2*)&out[(size_t)n * HC + lane * 2] = make_float2(acc0, acc1);
}

// ---------------- launch: fork-join overlap of CSR build and GEMM --------
extern "C" void kernel_launch(void* const* d_in, const int* in_sizes, int n_in,
                              void* d_out, int out_size) {
    const float* x     = (const float*)d_in[0];
    const int*   ei    = (const int*)d_in[1];
    const float* W     = (const float*)d_in[2];
    const float* a_src = (const float*)d_in[3];
    const float* a_dst = (const float*)d_in[4];
    float* out = (float*)d_out;

    int v    = in_sizes[0] / IN_CH;
    int ecnt = in_sizes[1] / 2;
    int nb   = (v + SCAN_BLK - 1) / SCAN_BLK;

    static cudaStream_t s2 = nullptr;
    static cudaEvent_t evFork = nullptr, evJoin = nullptr;
    if (s2 == nullptr) {
        cudaStreamCreateWithFlags(&s2, cudaStreamNonBlocking);
        cudaEventCreateWithFlags(&evFork, cudaEventDisableTiming);
        cudaEventCreateWithFlags(&evJoin, cudaEventDisableTiming);
    }

    const int smem = (IN_CH * WPAD * 2 + 128) * sizeof(float);
    cudaFuncSetAttribute(gemm_logits_kernel,
                         cudaFuncAttributeMaxDynamicSharedMemorySize, smem);

    cudaEventRecord(evFork, 0);
    cudaStreamWaitEvent(s2, evFork, 0);

    zero_deg_kernel<<<(v + 255) / 256, 256, 0, s2>>>(v);
    count_kernel<<<(ecnt + 255) / 256, 256, 0, s2>>>(ei, ecnt);
    scan1_kernel<<<nb, SCAN_BLK, 0, s2>>>(v);

    gemm_logits_kernel<<<(v + GROWS - 1) / GROWS, 256, smem>>>(x, W, a_src, a_dst, v);

    scan3_kernel<<<nb, SCAN_BLK, 0, s2>>>(v);
    scatter_kernel<<<(ecnt + 255) / 256, 256, 0, s2>>>(ei, ecnt);

    cudaEventRecord(evJoin, s2);
    cudaStreamWaitEvent(0, evJoin, 0);
    node_agg_kernel<<<(v + 7) / 8, 256>>>(out, v);
}

// round 15
// speedup vs baseline: 1.2741x; 1.2741x over previous
#include <cuda_runtime.h>
#include <math.h>

#define V_MAX   100000
#define E_MAX   1600000
#define IN_CH   128
#define HEADS   4
#define HC      64
#define NEG_SLOPE 0.2f
#define SCAN_BLK 256
#define GROWS   128
#define WPAD    72

// ---------------- scratch (device globals; no allocation) ----------------
__device__ float g_z[(size_t)V_MAX * HC];
__device__ float g_esrc[V_MAX * HEADS];
__device__ float g_edst[V_MAX * HEADS];
__device__ int   g_deg[V_MAX];
__device__ int   g_excl[V_MAX];
__device__ int   g_bsums[512];
__device__ int   g_rowstart[V_MAX];
__device__ int   g_cursor[V_MAX];
__device__ int   g_csr_src[E_MAX];

// ---------------- CSR build ----------------
__global__ void zero_deg_kernel(int v) {
    int i = blockIdx.x * blockDim.x + threadIdx.x;
    if (i < v) g_deg[i] = 0;
}

__global__ void count_kernel(const int* __restrict__ ei, int ecnt) {
    int e = blockIdx.x * blockDim.x + threadIdx.x;
    if (e < ecnt) atomicAdd(&g_deg[ei[ecnt + e]], 1);
}

__global__ void scan1_kernel(int v) {
    __shared__ int sh[SCAN_BLK];
    int t = threadIdx.x;
    int i = blockIdx.x * SCAN_BLK + t;
    int val = (i < v) ? g_deg[i] : 0;
    sh[t] = val;
    __syncthreads();
#pragma unroll
    for (int off = 1; off < SCAN_BLK; off <<= 1) {
        int y = (t >= off) ? sh[t - off] : 0;
        __syncthreads();
        sh[t] += y;
        __syncthreads();
    }
    if (i < v) g_excl[i] = sh[t] - val;
    if (t == SCAN_BLK - 1) g_bsums[blockIdx.x] = sh[t];
}

__global__ void scan3_kernel(int v) {
    __shared__ int red[SCAN_BLK];
    const int b = blockIdx.x;
    const int t = threadIdx.x;
    int sum = 0;
    for (int i = t; i < b; i += SCAN_BLK) sum += g_bsums[i];
    red[t] = sum;
    __syncthreads();
#pragma unroll
    for (int off = SCAN_BLK / 2; off; off >>= 1) {
        if (t < off) red[t] += red[t + off];
        __syncthreads();
    }
    int prefix = red[0];
    int i = b * SCAN_BLK + t;
    if (i < v) {
        int r = g_excl[i] + prefix;
        g_rowstart[i] = r;
        g_cursor[i]   = r;
    }
}

__global__ void scatter_kernel(const int* __restrict__ ei, int ecnt) {
    int e = blockIdx.x * blockDim.x + threadIdx.x;
    if (e >= ecnt) return;
    int s = ei[e];
    int d = ei[ecnt + e];
    int pos = atomicAdd(&g_cursor[d], 1);
    g_csr_src[pos] = s;
}

// ---------------- helpers for tf32 mma ----------------
__device__ __forceinline__ unsigned cvt_tf32(float f) {
    unsigned u;
    asm("cvt.rna.tf32.f32 %0, %1;" : "=r"(u) : "f"(f));
    return u;
}

__device__ __forceinline__ void mma_tf32(float& c0, float& c1, float& c2, float& c3,
                                         unsigned a0, unsigned a1, unsigned a2, unsigned a3,
                                         unsigned b0, unsigned b1) {
    asm("mma.sync.aligned.m16n8k8.row.col.f32.tf32.tf32.f32 "
        "{%0,%1,%2,%3}, {%4,%5,%6,%7}, {%8,%9}, {%0,%1,%2,%3};"
        : "+f"(c0), "+f"(c1), "+f"(c2), "+f"(c3)
        : "r"(a0), "r"(a1), "r"(a2), "r"(a3), "r"(b0), "r"(b1));
}

// ---------------- fused GEMM + logits (tf32, 3xTF32) — R11 proven, frozen
__global__ void __launch_bounds__(256, 2)
gemm_logits_kernel(const float* __restrict__ x,
                   const float* __restrict__ W,
                   const float* __restrict__ a_src,
                   const float* __restrict__ a_dst,
                   int v)
{
    extern __shared__ float sm[];
    float* Whi = sm;
    float* Wlo = Whi + IN_CH * WPAD;
    float* as  = Wlo + IN_CH * WPAD;
    float* ad  = as + 64;

    const int tid  = threadIdx.x;
    const int wid  = tid >> 5;
    const int lane = tid & 31;
    const int g = lane >> 2;
    const int t = lane & 3;
    const int row0 = blockIdx.x * GROWS;

    for (int i = tid; i < IN_CH * HC; i += 256) {
        int k = i >> 6, n = i & 63;
        float w = W[i];
        unsigned hu = cvt_tf32(w);
        float hf = __uint_as_float(hu);
        Whi[k * WPAD + n] = hf;
        Wlo[k * WPAD + n] = __uint_as_float(cvt_tf32(w - hf));
    }
    if (tid < 64)       as[tid]      = a_src[tid];
    else if (tid < 128) ad[tid - 64] = a_dst[tid - 64];
    __syncthreads();

    float c0[8], c1[8], c2[8], c3[8];
#pragma unroll
    for (int nt = 0; nt < 8; ++nt) { c0[nt] = c1[nt] = c2[nt] = c3[nt] = 0.f; }

    const int r_lo = row0 + wid * 16 + g;
    const int r_hi = r_lo + 8;
    const bool vlo = r_lo < v, vhi = r_hi < v;
    const float* xlo = x + (size_t)r_lo * IN_CH;
    const float* xhi = x + (size_t)r_hi * IN_CH;

#pragma unroll 2
    for (int ks = 0; ks < IN_CH / 8; ++ks) {
        const int k0 = ks * 8;
        float a0f = vlo ? xlo[k0 + t]     : 0.f;
        float a1f = vhi ? xhi[k0 + t]     : 0.f;
        float a2f = vlo ? xlo[k0 + t + 4] : 0.f;
        float a3f = vhi ? xhi[k0 + t + 4] : 0.f;

        unsigned a0h = cvt_tf32(a0f), a1h = cvt_tf32(a1f);
        unsigned a2h = cvt_tf32(a2f), a3h = cvt_tf32(a3f);
        unsigned a0l = cvt_tf32(a0f - __uint_as_float(a0h));
        unsigned a1l = cvt_tf32(a1f - __uint_as_float(a1h));
        unsigned a2l = cvt_tf32(a2f - __uint_as_float(a2h));
        unsigned a3l = cvt_tf32(a3f - __uint_as_float(a3h));

        const int krow0 = (k0 + t) * WPAD;
        const int krow1 = (k0 + t + 4) * WPAD;
#pragma unroll
        for (int nt = 0; nt < 8; ++nt) {
            int col = nt * 8 + g;
            unsigned b0h = __float_as_uint(Whi[krow0 + col]);
            unsigned b1h = __float_as_uint(Whi[krow1 + col]);
            unsigned b0l = __float_as_uint(Wlo[krow0 + col]);
            unsigned b1l = __float_as_uint(Wlo[krow1 + col]);
            mma_tf32(c0[nt], c1[nt], c2[nt], c3[nt], a0h, a1h, a2h, a3h, b0h, b1h);
            mma_tf32(c0[nt], c1[nt], c2[nt], c3[nt], a0h, a1h, a2h, a3h, b0l, b1l);
            mma_tf32(c0[nt], c1[nt], c2[nt], c3[nt], a0l, a1l, a2l, a3l, b0h, b1h);
        }
    }

    if (vlo) {
#pragma unroll
        for (int nt = 0; nt < 8; ++nt)
            *(float2*)&g_z[(size_t)r_lo * HC + nt * 8 + 2 * t] = make_float2(c0[nt], c1[nt]);
    }
    if (vhi) {
#pragma unroll
        for (int nt = 0; nt < 8; ++nt)
            *(float2*)&g_z[(size_t)r_hi * HC + nt * 8 + 2 * t] = make_float2(c2[nt], c3[nt]);
    }

#pragma unroll
    for (int h = 0; h < HEADS; ++h) {
        float s0 = as[h * 16 + 2 * t],     s1 = as[h * 16 + 2 * t + 1];
        float s2 = as[h * 16 + 8 + 2 * t], s3 = as[h * 16 + 8 + 2 * t + 1];
        float d0 = ad[h * 16 + 2 * t],     d1 = ad[h * 16 + 2 * t + 1];
        float d2 = ad[h * 16 + 8 + 2 * t], d3 = ad[h * 16 + 8 + 2 * t + 1];

        float psl = c0[2*h]*s0 + c1[2*h]*s1 + c0[2*h+1]*s2 + c1[2*h+1]*s3;
        float pdl = c0[2*h]*d0 + c1[2*h]*d1 + c0[2*h+1]*d2 + c1[2*h+1]*d3;
        float psh = c2[2*h]*s0 + c3[2*h]*s1 + c2[2*h+1]*s2 + c3[2*h+1]*s3;
        float pdh = c2[2*h]*d0 + c3[2*h]*d1 + c2[2*h+1]*d2 + c3[2*h+1]*d3;

        psl += __shfl_xor_sync(0xffffffffu, psl, 1);
        psl += __shfl_xor_sync(0xffffffffu, psl, 2);
        pdl += __shfl_xor_sync(0xffffffffu, pdl, 1);
        pdl += __shfl_xor_sync(0xffffffffu, pdl, 2);
        psh += __shfl_xor_sync(0xffffffffu, psh, 1);
        psh += __shfl_xor_sync(0xffffffffu, psh, 2);
        pdh += __shfl_xor_sync(0xffffffffu, pdh, 1);
        pdh += __shfl_xor_sync(0xffffffffu, pdh, 2);

        if (t == 0) {
            if (vlo) {
                g_esrc[r_lo * HEADS + h] = psl;
                g_edst[r_lo * HEADS + h] = pdl;
            }
            if (vhi) {
                g_esrc[r_hi * HEADS + h] = psh;
                g_edst[r_hi * HEADS + h] = pdh;
            }
        }
    }
}

// ---------------- fused softmax + aggregation (CSR, pair-lane gathers) ---
// R12 phase structure. Lane mapping changed: lanes 0-15 handle edge j,
// lanes 16-31 edge j+1, float4 (4 channels) per lane -> each LDG.128
// covers TWO edges (half the load instructions, 2x edges in flight).
// Staged entries beyond cnt are zero (alpha=0, src=0) so pair loop is safe.
__global__ void node_agg_kernel(float* __restrict__ out, int v) {
    __shared__ int   sh_s[8][32];
    __shared__ float sh_a[8][32][4];

    const int wid  = threadIdx.x >> 5;
    const int lane = threadIdx.x & 31;
    const int n = blockIdx.x * 8 + wid;
    if (n >= v) return;

    const int start = g_rowstart[n];
    const int degn  = g_deg[n];
    const float4 ed = *(const float4*)&g_edst[n * 4];
    const int lt    = lane & 15;         // channel-lane: owns channels [4lt,4lt+4)
    const int half  = lane >> 4;         // 0: even edge of pair, 1: odd edge
    const int head  = lt >> 2;

    float4 acc = make_float4(0.f, 0.f, 0.f, 0.f);
    float d0 = 0.f, d1 = 0.f, d2 = 0.f, d3 = 0.f;

    for (int i0 = 0; i0 < degn; i0 += 32) {
        // ---- stage 32 edges: src + exp weights (full 32-lane parallel) ----
        int idx = i0 + lane;
        int s = 0;
        float ex0 = 0.f, ex1 = 0.f, ex2 = 0.f, ex3 = 0.f;
        if (idx < degn) {
            s = __ldg(&g_csr_src[start + idx]);
            float4 es = *(const float4*)&g_esrc[s * 4];
            float w;
            w = es.x + ed.x; w = w > 0.f ? w : NEG_SLOPE * w; ex0 = __expf(w);
            w = es.y + ed.y; w = w > 0.f ? w : NEG_SLOPE * w; ex1 = __expf(w);
            w = es.z + ed.z; w = w > 0.f ? w : NEG_SLOPE * w; ex2 = __expf(w);
            w = es.w + ed.w; w = w > 0.f ? w : NEG_SLOPE * w; ex3 = __expf(w);
        }
        d0 += ex0; d1 += ex1; d2 += ex2; d3 += ex3;
        sh_s[wid][lane] = s;
        *(float4*)&sh_a[wid][lane][0] = make_float4(ex0, ex1, ex2, ex3);
        __syncwarp();

        int cnt = min(degn - i0, 32);
        int jmax = (cnt + 1) & ~1;       // even; padded entries are zero
        const float* zb = g_z + lt * 4;
        int j = 0;
        // 8 LDG.128 in flight = 16 edges per group
        for (; j + 16 <= jmax; j += 16) {
            int    sj[8];
            float4 zj[8];
            float  aj[8];
#pragma unroll
            for (int u = 0; u < 8; ++u) sj[u] = sh_s[wid][j + 2 * u + half];
#pragma unroll
            for (int u = 0; u < 8; ++u) zj[u] = *(const float4*)(zb + (size_t)sj[u] * HC);
#pragma unroll
            for (int u = 0; u < 8; ++u) aj[u] = sh_a[wid][j + 2 * u + half][head];
#pragma unroll
            for (int u = 0; u < 8; ++u) {
                acc.x += zj[u].x * aj[u];
                acc.y += zj[u].y * aj[u];
                acc.z += zj[u].z * aj[u];
                acc.w += zj[u].w * aj[u];
            }
        }
        for (; j < jmax; j += 2) {
            int   sj = sh_s[wid][j + half];
            float a  = sh_a[wid][j + half][head];
            float4 zv = *(const float4*)(zb + (size_t)sj * HC);
            acc.x += zv.x * a; acc.y += zv.y * a;
            acc.z += zv.z * a; acc.w += zv.w * a;
        }
        __syncwarp();
    }

    // reduce denominators across the warp
#pragma unroll
    for (int o = 16; o; o >>= 1) {
        d0 += __shfl_xor_sync(0xffffffffu, d0, o);
        d1 += __shfl_xor_sync(0xffffffffu, d1, o);
        d2 += __shfl_xor_sync(0xffffffffu, d2, o);
        d3 += __shfl_xor_sync(0xffffffffu, d3, o);
    }
    // combine even/odd halves (lane l and l+16 hold same channels)
    acc.x += __shfl_xor_sync(0xffffffffu, acc.x, 16);
    acc.y += __shfl_xor_sync(0xffffffffu, acc.y, 16);
    acc.z += __shfl_xor_sync(0xffffffffu, acc.z, 16);
    acc.w += __shfl_xor_sync(0xffffffffu, acc.w, 16);

    if (half == 0) {
        float den = head == 0 ? d0 : head == 1 ? d1 : head == 2 ? d2 : d3;
        float r = __frcp_rn(den + 1e-9f);
        float4 o4;
        o4.x = acc.x * r; o4.x = o4.x > 0.f ? o4.x : expm1f(o4.x);
        o4.y = acc.y * r; o4.y = o4.y > 0.f ? o4.y : expm1f(o4.y);
        o4.z = acc.z * r; o4.z = o4.z > 0.f ? o4.z : expm1f(o4.z);
        o4.w = acc.w * r; o4.w = o4.w > 0.f ? o4.w : expm1f(o4.w);
        *(float4*)&out[(size_t)n * HC + lt * 4] = o4;
    }
}

// ---------------- launch: fork-join overlap of CSR build and GEMM --------
extern "C" void kernel_launch(void* const* d_in, const int* in_sizes, int n_in,
                              void* d_out, int out_size) {
    const float* x     = (const float*)d_in[0];
    const int*   ei    = (const int*)d_in[1];
    const float* W     = (const float*)d_in[2];
    const float* a_src = (const float*)d_in[3];
    const float* a_dst = (const float*)d_in[4];
    float* out = (float*)d_out;

    int v    = in_sizes[0] / IN_CH;
    int ecnt = in_sizes[1] / 2;
    int nb   = (v + SCAN_BLK - 1) / SCAN_BLK;

    static cudaStream_t s2 = nullptr;
    static cudaEvent_t evFork = nullptr, evJoin = nullptr;
    if (s2 == nullptr) {
        cudaStreamCreateWithFlags(&s2, cudaStreamNonBlocking);
        cudaEventCreateWithFlags(&evFork, cudaEventDisableTiming);
        cudaEventCreateWithFlags(&evJoin, cudaEventDisableTiming);
    }

    const int smem = (IN_CH * WPAD * 2 + 128) * sizeof(float);
    cudaFuncSetAttribute(gemm_logits_kernel,
                         cudaFuncAttributeMaxDynamicSharedMemorySize, smem);

    cudaEventRecord(evFork, 0);
    cudaStreamWaitEvent(s2, evFork, 0);

    zero_deg_kernel<<<(v + 255) / 256, 256, 0, s2>>>(v);
    count_kernel<<<(ecnt + 255) / 256, 256, 0, s2>>>(ei, ecnt);
    scan1_kernel<<<nb, SCAN_BLK, 0, s2>>>(v);

    gemm_logits_kernel<<<(v + GROWS - 1) / GROWS, 256, smem>>>(x, W, a_src, a_dst, v);

    scan3_kernel<<<nb, SCAN_BLK, 0, s2>>>(v);
    scatter_kernel<<<(ecnt + 255) / 256, 256, 0, s2>>>(ei, ecnt);

    cudaEventRecord(evJoin, s2);
    cudaStreamWaitEvent(0, evJoin, 0);
    node_agg_kernel<<<(v + 7) / 8, 256>>>(out, v);
}

// round 16
// speedup vs baseline: 1.3367x; 1.0491x over previous
#include <cuda_runtime.h>
#include <math.h>

#define V_MAX   100000
#define E_MAX   1600000
#define IN_CH   128
#define HEADS   4
#define HC      64
#define NEG_SLOPE 0.2f
#define SCAN_BLK 256
#define GROWS   128
#define WPAD    72

// ---------------- scratch (device globals; no allocation) ----------------
__device__ float g_z[(size_t)V_MAX * HC];
__device__ float g_esrc[V_MAX * HEADS];
__device__ float g_edst[V_MAX * HEADS];
__device__ int   g_deg[V_MAX];
__device__ int   g_excl[V_MAX];
__device__ int   g_bsums[512];
__device__ int   g_rowstart[V_MAX];
__device__ int   g_cursor[V_MAX];
__device__ int   g_csr_src[E_MAX];

// ---------------- CSR build ----------------
__global__ void count_kernel(const int* __restrict__ ei, int ecnt) {
    int e = blockIdx.x * blockDim.x + threadIdx.x;
    if (e < ecnt) atomicAdd(&g_deg[ei[ecnt + e]], 1);
}

__global__ void scan1_kernel(int v) {
    __shared__ int sh[SCAN_BLK];
    int t = threadIdx.x;
    int i = blockIdx.x * SCAN_BLK + t;
    int val = (i < v) ? g_deg[i] : 0;
    sh[t] = val;
    __syncthreads();
#pragma unroll
    for (int off = 1; off < SCAN_BLK; off <<= 1) {
        int y = (t >= off) ? sh[t - off] : 0;
        __syncthreads();
        sh[t] += y;
        __syncthreads();
    }
    if (i < v) g_excl[i] = sh[t] - val;
    if (t == SCAN_BLK - 1) g_bsums[blockIdx.x] = sh[t];
}

__global__ void scan3_kernel(int v) {
    __shared__ int red[SCAN_BLK];
    const int b = blockIdx.x;
    const int t = threadIdx.x;
    int sum = 0;
    for (int i = t; i < b; i += SCAN_BLK) sum += g_bsums[i];
    red[t] = sum;
    __syncthreads();
#pragma unroll
    for (int off = SCAN_BLK / 2; off; off >>= 1) {
        if (t < off) red[t] += red[t + off];
        __syncthreads();
    }
    int prefix = red[0];
    int i = b * SCAN_BLK + t;
    if (i < v) {
        int r = g_excl[i] + prefix;
        g_rowstart[i] = r;
        g_cursor[i]   = r;
    }
}

__global__ void scatter_kernel(const int* __restrict__ ei, int ecnt) {
    int e = blockIdx.x * blockDim.x + threadIdx.x;
    if (e >= ecnt) return;
    int s = ei[e];
    int d = ei[ecnt + e];
    int pos = atomicAdd(&g_cursor[d], 1);
    g_csr_src[pos] = s;
}

// ---------------- helpers for tf32 mma ----------------
__device__ __forceinline__ unsigned cvt_tf32(float f) {
    unsigned u;
    asm("cvt.rna.tf32.f32 %0, %1;" : "=r"(u) : "f"(f));
    return u;
}

__device__ __forceinline__ void mma_tf32(float& c0, float& c1, float& c2, float& c3,
                                         unsigned a0, unsigned a1, unsigned a2, unsigned a3,
                                         unsigned b0, unsigned b1) {
    asm("mma.sync.aligned.m16n8k8.row.col.f32.tf32.tf32.f32 "
        "{%0,%1,%2,%3}, {%4,%5,%6,%7}, {%8,%9}, {%0,%1,%2,%3};"
        : "+f"(c0), "+f"(c1), "+f"(c2), "+f"(c3)
        : "r"(a0), "r"(a1), "r"(a2), "r"(a3), "r"(b0), "r"(b1));
}

// ---------------- fused GEMM + logits (tf32, 3xTF32) — R11 proven, frozen
__global__ void __launch_bounds__(256, 2)
gemm_logits_kernel(const float* __restrict__ x,
                   const float* __restrict__ W,
                   const float* __restrict__ a_src,
                   const float* __restrict__ a_dst,
                   int v)
{
    extern __shared__ float sm[];
    float* Whi = sm;
    float* Wlo = Whi + IN_CH * WPAD;
    float* as  = Wlo + IN_CH * WPAD;
    float* ad  = as + 64;

    const int tid  = threadIdx.x;
    const int wid  = tid >> 5;
    const int lane = tid & 31;
    const int g = lane >> 2;
    const int t = lane & 3;
    const int row0 = blockIdx.x * GROWS;

    for (int i = tid; i < IN_CH * HC; i += 256) {
        int k = i >> 6, n = i & 63;
        float w = W[i];
        unsigned hu = cvt_tf32(w);
        float hf = __uint_as_float(hu);
        Whi[k * WPAD + n] = hf;
        Wlo[k * WPAD + n] = __uint_as_float(cvt_tf32(w - hf));
    }
    if (tid < 64)       as[tid]      = a_src[tid];
    else if (tid < 128) ad[tid - 64] = a_dst[tid - 64];
    __syncthreads();

    float c0[8], c1[8], c2[8], c3[8];
#pragma unroll
    for (int nt = 0; nt < 8; ++nt) { c0[nt] = c1[nt] = c2[nt] = c3[nt] = 0.f; }

    const int r_lo = row0 + wid * 16 + g;
    const int r_hi = r_lo + 8;
    const bool vlo = r_lo < v, vhi = r_hi < v;
    const float* xlo = x + (size_t)r_lo * IN_CH;
    const float* xhi = x + (size_t)r_hi * IN_CH;

#pragma unroll 2
    for (int ks = 0; ks < IN_CH / 8; ++ks) {
        const int k0 = ks * 8;
        float a0f = vlo ? xlo[k0 + t]     : 0.f;
        float a1f = vhi ? xhi[k0 + t]     : 0.f;
        float a2f = vlo ? xlo[k0 + t + 4] : 0.f;
        float a3f = vhi ? xhi[k0 + t + 4] : 0.f;

        unsigned a0h = cvt_tf32(a0f), a1h = cvt_tf32(a1f);
        unsigned a2h = cvt_tf32(a2f), a3h = cvt_tf32(a3f);
        unsigned a0l = cvt_tf32(a0f - __uint_as_float(a0h));
        unsigned a1l = cvt_tf32(a1f - __uint_as_float(a1h));
        unsigned a2l = cvt_tf32(a2f - __uint_as_float(a2h));
        unsigned a3l = cvt_tf32(a3f - __uint_as_float(a3h));

        const int krow0 = (k0 + t) * WPAD;
        const int krow1 = (k0 + t + 4) * WPAD;
#pragma unroll
        for (int nt = 0; nt < 8; ++nt) {
            int col = nt * 8 + g;
            unsigned b0h = __float_as_uint(Whi[krow0 + col]);
            unsigned b1h = __float_as_uint(Whi[krow1 + col]);
            unsigned b0l = __float_as_uint(Wlo[krow0 + col]);
            unsigned b1l = __float_as_uint(Wlo[krow1 + col]);
            mma_tf32(c0[nt], c1[nt], c2[nt], c3[nt], a0h, a1h, a2h, a3h, b0h, b1h);
            mma_tf32(c0[nt], c1[nt], c2[nt], c3[nt], a0h, a1h, a2h, a3h, b0l, b1l);
            mma_tf32(c0[nt], c1[nt], c2[nt], c3[nt], a0l, a1l, a2l, a3l, b0h, b1h);
        }
    }

    if (vlo) {
#pragma unroll
        for (int nt = 0; nt < 8; ++nt)
            *(float2*)&g_z[(size_t)r_lo * HC + nt * 8 + 2 * t] = make_float2(c0[nt], c1[nt]);
    }
    if (vhi) {
#pragma unroll
        for (int nt = 0; nt < 8; ++nt)
            *(float2*)&g_z[(size_t)r_hi * HC + nt * 8 + 2 * t] = make_float2(c2[nt], c3[nt]);
    }

#pragma unroll
    for (int h = 0; h < HEADS; ++h) {
        float s0 = as[h * 16 + 2 * t],     s1 = as[h * 16 + 2 * t + 1];
        float s2 = as[h * 16 + 8 + 2 * t], s3 = as[h * 16 + 8 + 2 * t + 1];
        float d0 = ad[h * 16 + 2 * t],     d1 = ad[h * 16 + 2 * t + 1];
        float d2 = ad[h * 16 + 8 + 2 * t], d3 = ad[h * 16 + 8 + 2 * t + 1];

        float psl = c0[2*h]*s0 + c1[2*h]*s1 + c0[2*h+1]*s2 + c1[2*h+1]*s3;
        float pdl = c0[2*h]*d0 + c1[2*h]*d1 + c0[2*h+1]*d2 + c1[2*h+1]*d3;
        float psh = c2[2*h]*s0 + c3[2*h]*s1 + c2[2*h+1]*s2 + c3[2*h+1]*s3;
        float pdh = c2[2*h]*d0 + c3[2*h]*d1 + c2[2*h+1]*d2 + c3[2*h+1]*d3;

        psl += __shfl_xor_sync(0xffffffffu, psl, 1);
        psl += __shfl_xor_sync(0xffffffffu, psl, 2);
        pdl += __shfl_xor_sync(0xffffffffu, pdl, 1);
        pdl += __shfl_xor_sync(0xffffffffu, pdl, 2);
        psh += __shfl_xor_sync(0xffffffffu, psh, 1);
        psh += __shfl_xor_sync(0xffffffffu, psh, 2);
        pdh += __shfl_xor_sync(0xffffffffu, pdh, 1);
        pdh += __shfl_xor_sync(0xffffffffu, pdh, 2);

        if (t == 0) {
            if (vlo) {
                g_esrc[r_lo * HEADS + h] = psl;
                g_edst[r_lo * HEADS + h] = pdl;
            }
            if (vhi) {
                g_esrc[r_hi * HEADS + h] = psh;
                g_edst[r_hi * HEADS + h] = pdh;
            }
        }
    }
}

// ---------------- fused softmax + aggregation — R12 proven, exact --------
__global__ void node_agg_kernel(float* __restrict__ out, int v) {
    __shared__ int   sh_s[8][32];
    __shared__ float sh_a[8][32][4];

    const int wid  = threadIdx.x >> 5;
    const int lane = threadIdx.x & 31;
    const int n = blockIdx.x * 8 + wid;
    if (n >= v) return;

    const int start = g_rowstart[n];
    const int degn  = g_deg[n];
    const float4 ed = *(const float4*)&g_edst[n * 4];
    const int head  = lane >> 3;

    float acc0 = 0.f, acc1 = 0.f;
    float d0 = 0.f, d1 = 0.f, d2 = 0.f, d3 = 0.f;

    for (int i0 = 0; i0 < degn; i0 += 32) {
        int idx = i0 + lane;
        int s = 0;
        float ex0 = 0.f, ex1 = 0.f, ex2 = 0.f, ex3 = 0.f;
        if (idx < degn) {
            s = __ldg(&g_csr_src[start + idx]);
            float4 es = *(const float4*)&g_esrc[s * 4];
            float w;
            w = es.x + ed.x; w = w > 0.f ? w : NEG_SLOPE * w; ex0 = __expf(w);
            w = es.y + ed.y; w = w > 0.f ? w : NEG_SLOPE * w; ex1 = __expf(w);
            w = es.z + ed.z; w = w > 0.f ? w : NEG_SLOPE * w; ex2 = __expf(w);
            w = es.w + ed.w; w = w > 0.f ? w : NEG_SLOPE * w; ex3 = __expf(w);
        }
        d0 += ex0; d1 += ex1; d2 += ex2; d3 += ex3;
        sh_s[wid][lane] = s;
        *(float4*)&sh_a[wid][lane][0] = make_float4(ex0, ex1, ex2, ex3);
        __syncwarp();

        int cnt = degn - i0; if (cnt > 32) cnt = 32;
        const float* zb = g_z + (size_t)lane * 2;
        int j = 0;
        for (; j + 8 <= cnt; j += 8) {
            int    sj[8];
            float2 zj[8];
            float  aj[8];
#pragma unroll
            for (int u = 0; u < 8; ++u) sj[u] = sh_s[wid][j + u];
#pragma unroll
            for (int u = 0; u < 8; ++u) zj[u] = *(const float2*)(zb + (size_t)sj[u] * HC);
#pragma unroll
            for (int u = 0; u < 8; ++u) aj[u] = sh_a[wid][j + u][head];
#pragma unroll
            for (int u = 0; u < 8; ++u) {
                acc0 += zj[u].x * aj[u];
                acc1 += zj[u].y * aj[u];
            }
        }
        for (; j < cnt; ++j) {
            int sj = sh_s[wid][j];
            float a = sh_a[wid][j][head];
            float2 zv = *(const float2*)(zb + (size_t)sj * HC);
            acc0 += zv.x * a; acc1 += zv.y * a;
        }
        __syncwarp();
    }

#pragma unroll
    for (int o = 16; o; o >>= 1) {
        d0 += __shfl_xor_sync(0xffffffffu, d0, o);
        d1 += __shfl_xor_sync(0xffffffffu, d1, o);
        d2 += __shfl_xor_sync(0xffffffffu, d2, o);
        d3 += __shfl_xor_sync(0xffffffffu, d3, o);
    }
    float den = head == 0 ? d0 : head == 1 ? d1 : head == 2 ? d2 : d3;
    float r = __frcp_rn(den + 1e-9f);
    acc0 *= r; acc1 *= r;
    acc0 = acc0 > 0.f ? acc0 : expm1f(acc0);
    acc1 = acc1 > 0.f ? acc1 : expm1f(acc1);
    *(float2*)&out[(size_t)n * HC + lane * 2] = make_float2(acc0, acc1);
}

// ---------------- launch: fork-join; memset replaces zero_deg kernel -----
// Kernel launch order: count(1), scan1(2), gemm(3), scan3(4), scatter(5),
// node_agg(6) — the profiler (skip 5) now lands on node_agg.
extern "C" void kernel_launch(void* const* d_in, const int* in_sizes, int n_in,
                              void* d_out, int out_size) {
    const float* x     = (const float*)d_in[0];
    const int*   ei    = (const int*)d_in[1];
    const float* W     = (const float*)d_in[2];
    const float* a_src = (const float*)d_in[3];
    const float* a_dst = (const float*)d_in[4];
    float* out = (float*)d_out;

    int v    = in_sizes[0] / IN_CH;
    int ecnt = in_sizes[1] / 2;
    int nb   = (v + SCAN_BLK - 1) / SCAN_BLK;

    static cudaStream_t s2 = nullptr;
    static cudaEvent_t evFork = nullptr, evJoin = nullptr;
    static void* degAddr = nullptr;
    if (s2 == nullptr) {
        cudaStreamCreateWithFlags(&s2, cudaStreamNonBlocking);
        cudaEventCreateWithFlags(&evFork, cudaEventDisableTiming);
        cudaEventCreateWithFlags(&evJoin, cudaEventDisableTiming);
        cudaGetSymbolAddress(&degAddr, g_deg);
    }

    const int smem = (IN_CH * WPAD * 2 + 128) * sizeof(float);
    cudaFuncSetAttribute(gemm_logits_kernel,
                         cudaFuncAttributeMaxDynamicSharedMemorySize, smem);

    cudaEventRecord(evFork, 0);
    cudaStreamWaitEvent(s2, evFork, 0);

    cudaMemsetAsync(degAddr, 0, (size_t)v * sizeof(int), s2);
    count_kernel<<<(ecnt + 255) / 256, 256, 0, s2>>>(ei, ecnt);
    scan1_kernel<<<nb, SCAN_BLK, 0, s2>>>(v);

    gemm_logits_kernel<<<(v + GROWS - 1) / GROWS, 256, smem>>>(x, W, a_src, a_dst, v);

    scan3_kernel<<<nb, SCAN_BLK, 0, s2>>>(v);
    scatter_kernel<<<(ecnt + 255) / 256, 256, 0, s2>>>(ei, ecnt);

    cudaEventRecord(evJoin, s2);
    cudaStreamWaitEvent(0, evJoin, 0);
    node_agg_kernel<<<(v + 7) / 8, 256>>>(out, v);
}

// round 17
// speedup vs baseline: 1.3914x; 1.0409x over previous
#include <cuda_runtime.h>
#include <cuda_fp16.h>
#include <math.h>

#define V_MAX   100000
#define E_MAX   1600000
#define IN_CH   128
#define HEADS   4
#define HC      64
#define NEG_SLOPE 0.2f
#define SCAN_BLK 256
#define GROWS   128
#define WPAD    72

// ---------------- scratch (device globals; no allocation) ----------------
__device__ unsigned g_zh[(size_t)V_MAX * 32];   // z as half2 pairs [V][32]
__device__ float g_esrc[V_MAX * HEADS];
__device__ float g_edst[V_MAX * HEADS];
__device__ int   g_deg[V_MAX];
__device__ int   g_excl[V_MAX];
__device__ int   g_bsums[512];
__device__ int   g_rowstart[V_MAX];
__device__ int   g_cursor[V_MAX];
__device__ int   g_csr_src[E_MAX];

// ---------------- CSR build ----------------
__global__ void count_kernel(const int* __restrict__ ei, int ecnt) {
    int e = blockIdx.x * blockDim.x + threadIdx.x;
    if (e < ecnt) atomicAdd(&g_deg[ei[ecnt + e]], 1);
}

__global__ void scan1_kernel(int v) {
    __shared__ int sh[SCAN_BLK];
    int t = threadIdx.x;
    int i = blockIdx.x * SCAN_BLK + t;
    int val = (i < v) ? g_deg[i] : 0;
    sh[t] = val;
    __syncthreads();
#pragma unroll
    for (int off = 1; off < SCAN_BLK; off <<= 1) {
        int y = (t >= off) ? sh[t - off] : 0;
        __syncthreads();
        sh[t] += y;
        __syncthreads();
    }
    if (i < v) g_excl[i] = sh[t] - val;
    if (t == SCAN_BLK - 1) g_bsums[blockIdx.x] = sh[t];
}

__global__ void scan3_kernel(int v) {
    __shared__ int red[SCAN_BLK];
    const int b = blockIdx.x;
    const int t = threadIdx.x;
    int sum = 0;
    for (int i = t; i < b; i += SCAN_BLK) sum += g_bsums[i];
    red[t] = sum;
    __syncthreads();
#pragma unroll
    for (int off = SCAN_BLK / 2; off; off >>= 1) {
        if (t < off) red[t] += red[t + off];
        __syncthreads();
    }
    int prefix = red[0];
    int i = b * SCAN_BLK + t;
    if (i < v) {
        int r = g_excl[i] + prefix;
        g_rowstart[i] = r;
        g_cursor[i]   = r;
    }
}

__global__ void scatter_kernel(const int* __restrict__ ei, int ecnt) {
    int e = blockIdx.x * blockDim.x + threadIdx.x;
    if (e >= ecnt) return;
    int s = ei[e];
    int d = ei[ecnt + e];
    int pos = atomicAdd(&g_cursor[d], 1);
    g_csr_src[pos] = s;
}

// ---------------- helpers for tf32 mma ----------------
__device__ __forceinline__ unsigned cvt_tf32(float f) {
    unsigned u;
    asm("cvt.rna.tf32.f32 %0, %1;" : "=r"(u) : "f"(f));
    return u;
}

__device__ __forceinline__ void mma_tf32(float& c0, float& c1, float& c2, float& c3,
                                         unsigned a0, unsigned a1, unsigned a2, unsigned a3,
                                         unsigned b0, unsigned b1) {
    asm("mma.sync.aligned.m16n8k8.row.col.f32.tf32.tf32.f32 "
        "{%0,%1,%2,%3}, {%4,%5,%6,%7}, {%8,%9}, {%0,%1,%2,%3};"
        : "+f"(c0), "+f"(c1), "+f"(c2), "+f"(c3)
        : "r"(a0), "r"(a1), "r"(a2), "r"(a3), "r"(b0), "r"(b1));
}

// ---------------- fused GEMM + logits (tf32, 3xTF32) — R11 frozen --------
// Only change: z stored as half2 (fp16) for the aggregation pass.
__global__ void __launch_bounds__(256, 2)
gemm_logits_kernel(const float* __restrict__ x,
                   const float* __restrict__ W,
                   const float* __restrict__ a_src,
                   const float* __restrict__ a_dst,
                   int v)
{
    extern __shared__ float sm[];
    float* Whi = sm;
    float* Wlo = Whi + IN_CH * WPAD;
    float* as  = Wlo + IN_CH * WPAD;
    float* ad  = as + 64;

    const int tid  = threadIdx.x;
    const int wid  = tid >> 5;
    const int lane = tid & 31;
    const int g = lane >> 2;
    const int t = lane & 3;
    const int row0 = blockIdx.x * GROWS;

    for (int i = tid; i < IN_CH * HC; i += 256) {
        int k = i >> 6, n = i & 63;
        float w = W[i];
        unsigned hu = cvt_tf32(w);
        float hf = __uint_as_float(hu);
        Whi[k * WPAD + n] = hf;
        Wlo[k * WPAD + n] = __uint_as_float(cvt_tf32(w - hf));
    }
    if (tid < 64)       as[tid]      = a_src[tid];
    else if (tid < 128) ad[tid - 64] = a_dst[tid - 64];
    __syncthreads();

    float c0[8], c1[8], c2[8], c3[8];
#pragma unroll
    for (int nt = 0; nt < 8; ++nt) { c0[nt] = c1[nt] = c2[nt] = c3[nt] = 0.f; }

    const int r_lo = row0 + wid * 16 + g;
    const int r_hi = r_lo + 8;
    const bool vlo = r_lo < v, vhi = r_hi < v;
    const float* xlo = x + (size_t)r_lo * IN_CH;
    const float* xhi = x + (size_t)r_hi * IN_CH;

#pragma unroll 2
    for (int ks = 0; ks < IN_CH / 8; ++ks) {
        const int k0 = ks * 8;
        float a0f = vlo ? xlo[k0 + t]     : 0.f;
        float a1f = vhi ? xhi[k0 + t]     : 0.f;
        float a2f = vlo ? xlo[k0 + t + 4] : 0.f;
        float a3f = vhi ? xhi[k0 + t + 4] : 0.f;

        unsigned a0h = cvt_tf32(a0f), a1h = cvt_tf32(a1f);
        unsigned a2h = cvt_tf32(a2f), a3h = cvt_tf32(a3f);
        unsigned a0l = cvt_tf32(a0f - __uint_as_float(a0h));
        unsigned a1l = cvt_tf32(a1f - __uint_as_float(a1h));
        unsigned a2l = cvt_tf32(a2f - __uint_as_float(a2h));
        unsigned a3l = cvt_tf32(a3f - __uint_as_float(a3h));

        const int krow0 = (k0 + t) * WPAD;
        const int krow1 = (k0 + t + 4) * WPAD;
#pragma unroll
        for (int nt = 0; nt < 8; ++nt) {
            int col = nt * 8 + g;
            unsigned b0h = __float_as_uint(Whi[krow0 + col]);
            unsigned b1h = __float_as_uint(Whi[krow1 + col]);
            unsigned b0l = __float_as_uint(Wlo[krow0 + col]);
            unsigned b1l = __float_as_uint(Wlo[krow1 + col]);
            mma_tf32(c0[nt], c1[nt], c2[nt], c3[nt], a0h, a1h, a2h, a3h, b0h, b1h);
            mma_tf32(c0[nt], c1[nt], c2[nt], c3[nt], a0h, a1h, a2h, a3h, b0l, b1l);
            mma_tf32(c0[nt], c1[nt], c2[nt], c3[nt], a0l, a1l, a2l, a3l, b0h, b1h);
        }
    }

    // store z as half2: row r, half2 index nt*4 + t (covers channels 2i,2i+1)
    if (vlo) {
#pragma unroll
        for (int nt = 0; nt < 8; ++nt) {
            __half2 hv = __floats2half2_rn(c0[nt], c1[nt]);
            g_zh[(size_t)r_lo * 32 + nt * 4 + t] = *(unsigned*)&hv;
        }
    }
    if (vhi) {
#pragma unroll
        for (int nt = 0; nt < 8; ++nt) {
            __half2 hv = __floats2half2_rn(c2[nt], c3[nt]);
            g_zh[(size_t)r_hi * 32 + nt * 4 + t] = *(unsigned*)&hv;
        }
    }

#pragma unroll
    for (int h = 0; h < HEADS; ++h) {
        float s0 = as[h * 16 + 2 * t],     s1 = as[h * 16 + 2 * t + 1];
        float s2 = as[h * 16 + 8 + 2 * t], s3 = as[h * 16 + 8 + 2 * t + 1];
        float d0 = ad[h * 16 + 2 * t],     d1 = ad[h * 16 + 2 * t + 1];
        float d2 = ad[h * 16 + 8 + 2 * t], d3 = ad[h * 16 + 8 + 2 * t + 1];

        float psl = c0[2*h]*s0 + c1[2*h]*s1 + c0[2*h+1]*s2 + c1[2*h+1]*s3;
        float pdl = c0[2*h]*d0 + c1[2*h]*d1 + c0[2*h+1]*d2 + c1[2*h+1]*d3;
        float psh = c2[2*h]*s0 + c3[2*h]*s1 + c2[2*h+1]*s2 + c3[2*h+1]*s3;
        float pdh = c2[2*h]*d0 + c3[2*h]*d1 + c2[2*h+1]*d2 + c3[2*h+1]*d3;

        psl += __shfl_xor_sync(0xffffffffu, psl, 1);
        psl += __shfl_xor_sync(0xffffffffu, psl, 2);
        pdl += __shfl_xor_sync(0xffffffffu, pdl, 1);
        pdl += __shfl_xor_sync(0xffffffffu, pdl, 2);
        psh += __shfl_xor_sync(0xffffffffu, psh, 1);
        psh += __shfl_xor_sync(0xffffffffu, psh, 2);
        pdh += __shfl_xor_sync(0xffffffffu, pdh, 1);
        pdh += __shfl_xor_sync(0xffffffffu, pdh, 2);

        if (t == 0) {
            if (vlo) {
                g_esrc[r_lo * HEADS + h] = psl;
                g_edst[r_lo * HEADS + h] = pdl;
            }
            if (vhi) {
                g_esrc[r_hi * HEADS + h] = psh;
                g_edst[r_hi * HEADS + h] = pdh;
            }
        }
    }
}

// ---------------- fused softmax + aggregation — R12 structure, fp16 z ----
// z row = 128B = ONE cache line; lane loads one half2 (LDG.32 coalesced).
// Halves the dominant L2 traffic (node_agg is LTS-cap bound).
__global__ void node_agg_kernel(float* __restrict__ out, int v) {
    __shared__ int   sh_s[8][32];
    __shared__ float sh_a[8][32][4];

    const int wid  = threadIdx.x >> 5;
    const int lane = threadIdx.x & 31;
    const int n = blockIdx.x * 8 + wid;
    if (n >= v) return;

    const int start = g_rowstart[n];
    const int degn  = g_deg[n];
    const float4 ed = *(const float4*)&g_edst[n * 4];
    const int head  = lane >> 3;

    float acc0 = 0.f, acc1 = 0.f;
    float d0 = 0.f, d1 = 0.f, d2 = 0.f, d3 = 0.f;

    for (int i0 = 0; i0 < degn; i0 += 32) {
        int idx = i0 + lane;
        int s = 0;
        float ex0 = 0.f, ex1 = 0.f, ex2 = 0.f, ex3 = 0.f;
        if (idx < degn) {
            s = __ldg(&g_csr_src[start + idx]);
            float4 es = *(const float4*)&g_esrc[s * 4];
            float w;
            w = es.x + ed.x; w = w > 0.f ? w : NEG_SLOPE * w; ex0 = __expf(w);
            w = es.y + ed.y; w = w > 0.f ? w : NEG_SLOPE * w; ex1 = __expf(w);
            w = es.z + ed.z; w = w > 0.f ? w : NEG_SLOPE * w; ex2 = __expf(w);
            w = es.w + ed.w; w = w > 0.f ? w : NEG_SLOPE * w; ex3 = __expf(w);
        }
        d0 += ex0; d1 += ex1; d2 += ex2; d3 += ex3;
        sh_s[wid][lane] = s;
        *(float4*)&sh_a[wid][lane][0] = make_float4(ex0, ex1, ex2, ex3);
        __syncwarp();

        int cnt = degn - i0; if (cnt > 32) cnt = 32;
        const unsigned* zb = g_zh + lane;
        int j = 0;
        for (; j + 8 <= cnt; j += 8) {
            int      sj[8];
            unsigned zj[8];
            float    aj[8];
#pragma unroll
            for (int u = 0; u < 8; ++u) sj[u] = sh_s[wid][j + u];
#pragma unroll
            for (int u = 0; u < 8; ++u) zj[u] = zb[(size_t)sj[u] * 32];
#pragma unroll
            for (int u = 0; u < 8; ++u) aj[u] = sh_a[wid][j + u][head];
#pragma unroll
            for (int u = 0; u < 8; ++u) {
                float2 zf = __half22float2(*(__half2*)&zj[u]);
                acc0 += zf.x * aj[u];
                acc1 += zf.y * aj[u];
            }
        }
        for (; j < cnt; ++j) {
            int sj = sh_s[wid][j];
            float a = sh_a[wid][j][head];
            unsigned zu = zb[(size_t)sj * 32];
            float2 zf = __half22float2(*(__half2*)&zu);
            acc0 += zf.x * a; acc1 += zf.y * a;
        }
        __syncwarp();
    }

#pragma unroll
    for (int o = 16; o; o >>= 1) {
        d0 += __shfl_xor_sync(0xffffffffu, d0, o);
        d1 += __shfl_xor_sync(0xffffffffu, d1, o);
        d2 += __shfl_xor_sync(0xffffffffu, d2, o);
        d3 += __shfl_xor_sync(0xffffffffu, d3, o);
    }
    float den = head == 0 ? d0 : head == 1 ? d1 : head == 2 ? d2 : d3;
    float r = __frcp_rn(den + 1e-9f);
    acc0 *= r; acc1 *= r;
    acc0 = acc0 > 0.f ? acc0 : expm1f(acc0);
    acc1 = acc1 > 0.f ? acc1 : expm1f(acc1);
    *(float2*)&out[(size_t)n * HC + lane * 2] = make_float2(acc0, acc1);
}

// ---------------- launch: fork-join; memset for degree zeroing -----------
extern "C" void kernel_launch(void* const* d_in, const int* in_sizes, int n_in,
                              void* d_out, int out_size) {
    const float* x     = (const float*)d_in[0];
    const int*   ei    = (const int*)d_in[1];
    const float* W     = (const float*)d_in[2];
    const float* a_src = (const float*)d_in[3];
    const float* a_dst = (const float*)d_in[4];
    float* out = (float*)d_out;

    int v    = in_sizes[0] / IN_CH;
    int ecnt = in_sizes[1] / 2;
    int nb   = (v + SCAN_BLK - 1) / SCAN_BLK;

    static cudaStream_t s2 = nullptr;
    static cudaEvent_t evFork = nullptr, evJoin = nullptr;
    static void* degAddr = nullptr;
    if (s2 == nullptr) {
        cudaStreamCreateWithFlags(&s2, cudaStreamNonBlocking);
        cudaEventCreateWithFlags(&evFork, cudaEventDisableTiming);
        cudaEventCreateWithFlags(&evJoin, cudaEventDisableTiming);
        cudaGetSymbolAddress(&degAddr, g_deg);
    }

    const int smem = (IN_CH * WPAD * 2 + 128) * sizeof(float);
    cudaFuncSetAttribute(gemm_logits_kernel,
                         cudaFuncAttributeMaxDynamicSharedMemorySize, smem);

    cudaEventRecord(evFork, 0);
    cudaStreamWaitEvent(s2, evFork, 0);

    cudaMemsetAsync(degAddr, 0, (size_t)v * sizeof(int), s2);
    count_kernel<<<(ecnt + 255) / 256, 256, 0, s2>>>(ei, ecnt);
    scan1_kernel<<<nb, SCAN_BLK, 0, s2>>>(v);

    gemm_logits_kernel<<<(v + GROWS - 1) / GROWS, 256, smem>>>(x, W, a_src, a_dst, v);

    scan3_kernel<<<nb, SCAN_BLK, 0, s2>>>(v);
    scatter_kernel<<<(ecnt + 255) / 256, 256, 0, s2>>>(ei, ecnt);

    cudaEventRecord(evJoin, s2);
    cudaStreamWaitEvent(0, evJoin, 0);
    node_agg_kernel<<<(v + 7) / 8, 256>>>(out, v);
}